// round 7
// baseline (speedup 1.0000x reference)
#include <cuda_runtime.h>
#include <math.h>

#define D_IN  1024
#define H1    128
#define QD    32
#define NKEYS 256
#define HALF  8
#define BM    64
#define FULLMASK 0xffffffffu

// smem layout (floats), BM=64:
//   phase1: Xs [32 k][64 row] @0 (2048), Ws [32][132] @2048 (4224) -> ends 6272
//   phase2: Hs [64][132] @0 (8448), W2s [32][129] @8448 (4128)     -> ends 12576
//   qS [64][32] @12576 (2048), idxS [64][16] @14624 (1024), wS @15648 (1024)
//   total = 16672 floats = 66688 bytes
#define SM_WS    2048
#define SM_W2S   8448
#define SM_QS    12576
#define SM_IDX   14624
#define SM_W     15648
#define SM_TOTAL 16672

__device__ __forceinline__ unsigned mono_f(float x) {
    unsigned u = __float_as_uint(x);
    return u ^ (unsigned)(((int)u >> 31) | 0x80000000);
}

__global__ __launch_bounds__(256) void fused_kernel(
    const float* __restrict__ x,  const float* __restrict__ W1,
    const float* __restrict__ b1, const float* __restrict__ W2,
    const float* __restrict__ b2, const float* __restrict__ keys,
    const float* __restrict__ values, float* __restrict__ out)
{
    extern __shared__ float smem[];
    float* Xs  = smem;             // [32 k][64 row]
    float* Ws  = smem + SM_WS;     // [32 k][132] k-major
    float* Hs  = smem;             // [64][132]
    float* W2s = smem + SM_W2S;    // [32 c][129 k]
    float* qS  = smem + SM_QS;     // [64][32]
    int*   idxS = (int*)(smem + SM_IDX);   // [64][16]
    float* wS  = smem + SM_W;      // [64][16]

    const int tid  = threadIdx.x;
    const int lane = tid & 31;
    const int wid  = tid >> 5;              // 0..7
    const int block_row = blockIdx.x * BM;

    // ---------------- Phase 1: h = relu(x @ W1^T + b1) -------------------
    // microtile 8 rows x 4 cols; thread grid 8 x 32
    const int trow = wid * 8;               // 0..56
    const int tcol = lane * 4;              // 0..124

    // loader mapping: X tile 64 rows x 32 k -> 2 float4 per thread
    const int xr  = tid >> 2;               // 0..63
    const int xk8 = (tid & 3) * 8;          // 0,8,16,24

    float acc[8][4];
#pragma unroll
    for (int r = 0; r < 8; r++)
#pragma unroll
        for (int c = 0; c < 4; c++) acc[r][c] = 0.f;

    const float* xBase = x + (size_t)block_row * D_IN;

    // W1 tile loader mapping: 128 n x 32 k = 1024 float4 -> 4 per thread
    int wn[4], wk[4];
#pragma unroll
    for (int i = 0; i < 4; i++) {
        int j = tid + i * 256;
        wn[i] = j >> 3;
        wk[i] = (j & 7) * 4;
    }

    float4 xa, xb_, wv[4];
    // prefetch tile 0
    xa  = *(const float4*)(xBase + (size_t)xr * D_IN + xk8);
    xb_ = *(const float4*)(xBase + (size_t)xr * D_IN + xk8 + 4);
#pragma unroll
    for (int i = 0; i < 4; i++)
        wv[i] = *(const float4*)(W1 + (size_t)wn[i] * D_IN + wk[i]);

    for (int t = 0; t < 32; t++) {
        __syncthreads();
        // store staged tile
        Xs[(xk8 + 0) * BM + xr] = xa.x;
        Xs[(xk8 + 1) * BM + xr] = xa.y;
        Xs[(xk8 + 2) * BM + xr] = xa.z;
        Xs[(xk8 + 3) * BM + xr] = xa.w;
        Xs[(xk8 + 4) * BM + xr] = xb_.x;
        Xs[(xk8 + 5) * BM + xr] = xb_.y;
        Xs[(xk8 + 6) * BM + xr] = xb_.z;
        Xs[(xk8 + 7) * BM + xr] = xb_.w;
#pragma unroll
        for (int i = 0; i < 4; i++) {
            Ws[(wk[i] + 0) * 132 + wn[i]] = wv[i].x;
            Ws[(wk[i] + 1) * 132 + wn[i]] = wv[i].y;
            Ws[(wk[i] + 2) * 132 + wn[i]] = wv[i].z;
            Ws[(wk[i] + 3) * 132 + wn[i]] = wv[i].w;
        }
        __syncthreads();

        // prefetch next tile (overlaps with compute below)
        if (t + 1 < 32) {
            int k0 = (t + 1) * 32;
            xa  = *(const float4*)(xBase + (size_t)xr * D_IN + k0 + xk8);
            xb_ = *(const float4*)(xBase + (size_t)xr * D_IN + k0 + xk8 + 4);
#pragma unroll
            for (int i = 0; i < 4; i++)
                wv[i] = *(const float4*)(W1 + (size_t)wn[i] * D_IN + k0 + wk[i]);
        }

#pragma unroll 8
        for (int k = 0; k < 32; k++) {
            float4 r0 = *(const float4*)&Xs[k * BM + trow];
            float4 r1 = *(const float4*)&Xs[k * BM + trow + 4];
            float4 w4 = *(const float4*)&Ws[k * 132 + tcol];
            acc[0][0] = fmaf(r0.x, w4.x, acc[0][0]);
            acc[0][1] = fmaf(r0.x, w4.y, acc[0][1]);
            acc[0][2] = fmaf(r0.x, w4.z, acc[0][2]);
            acc[0][3] = fmaf(r0.x, w4.w, acc[0][3]);
            acc[1][0] = fmaf(r0.y, w4.x, acc[1][0]);
            acc[1][1] = fmaf(r0.y, w4.y, acc[1][1]);
            acc[1][2] = fmaf(r0.y, w4.z, acc[1][2]);
            acc[1][3] = fmaf(r0.y, w4.w, acc[1][3]);
            acc[2][0] = fmaf(r0.z, w4.x, acc[2][0]);
            acc[2][1] = fmaf(r0.z, w4.y, acc[2][1]);
            acc[2][2] = fmaf(r0.z, w4.z, acc[2][2]);
            acc[2][3] = fmaf(r0.z, w4.w, acc[2][3]);
            acc[3][0] = fmaf(r0.w, w4.x, acc[3][0]);
            acc[3][1] = fmaf(r0.w, w4.y, acc[3][1]);
            acc[3][2] = fmaf(r0.w, w4.z, acc[3][2]);
            acc[3][3] = fmaf(r0.w, w4.w, acc[3][3]);
            acc[4][0] = fmaf(r1.x, w4.x, acc[4][0]);
            acc[4][1] = fmaf(r1.x, w4.y, acc[4][1]);
            acc[4][2] = fmaf(r1.x, w4.z, acc[4][2]);
            acc[4][3] = fmaf(r1.x, w4.w, acc[4][3]);
            acc[5][0] = fmaf(r1.y, w4.x, acc[5][0]);
            acc[5][1] = fmaf(r1.y, w4.y, acc[5][1]);
            acc[5][2] = fmaf(r1.y, w4.z, acc[5][2]);
            acc[5][3] = fmaf(r1.y, w4.w, acc[5][3]);
            acc[6][0] = fmaf(r1.z, w4.x, acc[6][0]);
            acc[6][1] = fmaf(r1.z, w4.y, acc[6][1]);
            acc[6][2] = fmaf(r1.z, w4.z, acc[6][2]);
            acc[6][3] = fmaf(r1.z, w4.w, acc[6][3]);
            acc[7][0] = fmaf(r1.w, w4.x, acc[7][0]);
            acc[7][1] = fmaf(r1.w, w4.y, acc[7][1]);
            acc[7][2] = fmaf(r1.w, w4.z, acc[7][2]);
            acc[7][3] = fmaf(r1.w, w4.w, acc[7][3]);
        }
    }

    __syncthreads();   // done reading Xs/Ws; Hs overlays them

    // ---------------- Phase 2: q = relu_h @ W2^T + b2 --------------------
    {
        float4 b1v = *(const float4*)&b1[tcol];
#pragma unroll
        for (int r = 0; r < 8; r++) {
            float4 hv;
            hv.x = fmaxf(acc[r][0] + b1v.x, 0.f);
            hv.y = fmaxf(acc[r][1] + b1v.y, 0.f);
            hv.z = fmaxf(acc[r][2] + b1v.z, 0.f);
            hv.w = fmaxf(acc[r][3] + b1v.w, 0.f);
            *(float4*)&Hs[(trow + r) * 132 + tcol] = hv;
        }
        for (int i = tid; i < 32 * 128; i += 256) {
            int c = i >> 7, k = i & 127;
            W2s[c * 129 + k] = W2[i];
        }
    }
    __syncthreads();

    {
        const int rr = tid >> 2;            // 0..63
        const int cb = (tid & 3) * 8;       // 0,8,16,24
        float a2[8];
#pragma unroll
        for (int j = 0; j < 8; j++) a2[j] = 0.f;
#pragma unroll 4
        for (int k = 0; k < H1; k++) {
            float hv = Hs[rr * 132 + k];
#pragma unroll
            for (int j = 0; j < 8; j++)
                a2[j] = fmaf(hv, W2s[(cb + j) * 129 + k], a2[j]);
        }
        float4 q0, q1;
        q0.x = a2[0] + b2[cb + 0];
        q0.y = a2[1] + b2[cb + 1];
        q0.z = a2[2] + b2[cb + 2];
        q0.w = a2[3] + b2[cb + 3];
        q1.x = a2[4] + b2[cb + 4];
        q1.y = a2[5] + b2[cb + 5];
        q1.z = a2[6] + b2[cb + 6];
        q1.w = a2[7] + b2[cb + 7];
        *(float4*)&qS[rr * QD + cb]     = q0;
        *(float4*)&qS[rr * QD + cb + 4] = q1;
    }
    __syncthreads();

    // ---------------- Phase 3: topk per (token, head) --------------------
    for (int task = wid; task < 2 * BM; task += 8) {
        const int tl = task >> 1, h = task & 1;
        const float* qp = &qS[tl * QD + h * 16];

        float q1v[HALF], q2v[HALF];
#pragma unroll
        for (int c = 0; c < HALF; c++) { q1v[c] = qp[c]; q2v[c] = qp[HALF + c]; }

        float s1[8], s2[8];
        {
            const float4* k1 = (const float4*)(keys + ((size_t)(h * 2 + 0) * NKEYS + lane * 8) * HALF);
            const float4* k2 = (const float4*)(keys + ((size_t)(h * 2 + 1) * NKEYS + lane * 8) * HALF);
#pragma unroll
            for (int j = 0; j < 8; j++) {
                float4 u1 = k1[j * 2], v1 = k1[j * 2 + 1];
                float4 u2 = k2[j * 2], v2 = k2[j * 2 + 1];
                float a = 0.f, b = 0.f;
                a = fmaf(q1v[0], u1.x, a); a = fmaf(q1v[1], u1.y, a);
                a = fmaf(q1v[2], u1.z, a); a = fmaf(q1v[3], u1.w, a);
                a = fmaf(q1v[4], v1.x, a); a = fmaf(q1v[5], v1.y, a);
                a = fmaf(q1v[6], v1.z, a); a = fmaf(q1v[7], v1.w, a);
                b = fmaf(q2v[0], u2.x, b); b = fmaf(q2v[1], u2.y, b);
                b = fmaf(q2v[2], u2.z, b); b = fmaf(q2v[3], u2.w, b);
                b = fmaf(q2v[4], v2.x, b); b = fmaf(q2v[5], v2.y, b);
                b = fmaf(q2v[6], v2.z, b); b = fmaf(q2v[7], v2.w, b);
                s1[j] = a; s2[j] = b;
            }
        }

        float my_sc1 = 0.f, my_sc2 = 0.f;
        int   my_i1 = 0, my_i2 = 0;

        // top-8 of s1 via redux (exact monotone mapping; ties -> lowest index)
#pragma unroll
        for (int sel = 0; sel < 8; sel++) {
            float m = s1[0]; int mi = 0;
#pragma unroll
            for (int i = 1; i < 8; i++) if (s1[i] > m) { m = s1[i]; mi = i; }
            unsigned mm = mono_f(m);
            unsigned gm = __reduce_max_sync(FULLMASK, mm);
            unsigned bal = __ballot_sync(FULLMASK, mm == gm);
            int win = __ffs(bal) - 1;
            int   wmi = __shfl_sync(FULLMASK, mi, win);
            float wsc = __shfl_sync(FULLMASK, m, win);
            if (lane == sel) { my_sc1 = wsc; my_i1 = win * 8 + wmi; }
#pragma unroll
            for (int i = 0; i < 8; i++)
                if (lane == win && wmi == i) s1[i] = -INFINITY;
        }

#pragma unroll
        for (int sel = 0; sel < 8; sel++) {
            float m = s2[0]; int mi = 0;
#pragma unroll
            for (int i = 1; i < 8; i++) if (s2[i] > m) { m = s2[i]; mi = i; }
            unsigned mm = mono_f(m);
            unsigned gm = __reduce_max_sync(FULLMASK, mm);
            unsigned bal = __ballot_sync(FULLMASK, mm == gm);
            int win = __ffs(bal) - 1;
            int   wmi = __shfl_sync(FULLMASK, mi, win);
            float wsc = __shfl_sync(FULLMASK, m, win);
            if (lane == sel) { my_sc2 = wsc; my_i2 = win * 8 + wmi; }
#pragma unroll
            for (int i = 0; i < 8; i++)
                if (lane == win && wmi == i) s2[i] = -INFINITY;
        }

        // 64 combos, flat p = i*8+j; lane covers p=lane (slot0), p=lane+32 (slot1)
        float a0 = __shfl_sync(FULLMASK, my_sc1, lane >> 3);
        float a1 = __shfl_sync(FULLMASK, my_sc1, (lane >> 3) + 4);
        float b0 = __shfl_sync(FULLMASK, my_sc2, lane & 7);
        float cv0 = a0 + b0;
        float cv1 = a1 + b0;

        float my_fsc = -INFINITY; int my_fp = 0;
#pragma unroll
        for (int sel = 0; sel < 8; sel++) {
            float m = (cv0 >= cv1) ? cv0 : cv1;
            unsigned mm = mono_f(m);
            unsigned gm = __reduce_max_sync(FULLMASK, mm);
            unsigned bal0 = __ballot_sync(FULLMASK, mono_f(cv0) == gm);
            unsigned bal1 = __ballot_sync(FULLMASK, mono_f(cv1) == gm);
            int p_win = bal0 ? (__ffs(bal0) - 1) : (31 + __ffs(bal1));
            int winlane = p_win & 31;
            float wsc = __shfl_sync(FULLMASK, m, winlane);
            if (lane == sel) { my_fsc = wsc; my_fp = p_win; }
            if (lane == winlane) {
                if (p_win < 32) cv0 = -INFINITY; else cv1 = -INFINITY;
            }
        }

        // softmax over the 8 winners (lane 0 holds the max)
        float mx = __shfl_sync(FULLMASK, my_fsc, 0);
        float e = expf(my_fsc - mx);       // lanes >=8: exp(-inf)=0
        float sum = e;
#pragma unroll
        for (int off = 16; off; off >>= 1) sum += __shfl_xor_sync(FULLMASK, sum, off);
        float inv = 1.f / sum;

        int p  = my_fp;
        int ia = __shfl_sync(FULLMASK, my_i1, (p >> 3) & 31);
        int ib = __shfl_sync(FULLMASK, my_i2, p & 7);

        if (lane < 8) {
            idxS[tl * 16 + h * 8 + lane] = ia * NKEYS + ib;
            wS  [tl * 16 + h * 8 + lane] = e * inv;
        }
    }
    __syncthreads();

    // ---------------- Phase 4: gather ------------------------------------
    for (int tl = 0; tl < BM; tl++) {
        float4 acc4 = make_float4(0.f, 0.f, 0.f, 0.f);
#pragma unroll
        for (int k = 0; k < 16; k++) {
            int   idx = idxS[tl * 16 + k];
            float w   = wS [tl * 16 + k];
            float4 v = ((const float4*)(values + ((size_t)idx << 10)))[tid];
            acc4.x = fmaf(w, v.x, acc4.x);
            acc4.y = fmaf(w, v.y, acc4.y);
            acc4.z = fmaf(w, v.z, acc4.z);
            acc4.w = fmaf(w, v.w, acc4.w);
        }
        ((float4*)(out + ((size_t)(block_row + tl) << 10)))[tid] = acc4;
    }
}

extern "C" void kernel_launch(void* const* d_in, const int* in_sizes, int n_in,
                              void* d_out, int out_size)
{
    const float* x      = (const float*)d_in[0];
    const float* W1     = (const float*)d_in[1];
    const float* b1     = (const float*)d_in[2];
    const float* W2     = (const float*)d_in[3];
    const float* b2     = (const float*)d_in[4];
    const float* keys   = (const float*)d_in[5];
    const float* values = (const float*)d_in[6];
    float* out = (float*)d_out;

    const int T = in_sizes[0] / D_IN;   // 8192
    const int smemB = SM_TOTAL * (int)sizeof(float);  // 66688

    cudaFuncSetAttribute(fused_kernel,
                         cudaFuncAttributeMaxDynamicSharedMemorySize, smemB);

    fused_kernel<<<T / BM, 256, smemB>>>(x, W1, b1, W2, b2, keys, values, out);
}

// round 9
// speedup vs baseline: 1.6146x; 1.6146x over previous
#include <cuda_runtime.h>
#include <math.h>

#define D_IN  1024
#define H1    128
#define QD    32
#define NKEYS 256
#define HALF  8
#define FULLMASK 0xffffffffu

// smem layout (floats), BM=32:
//   phase1: Xs [32][36] @0 (1152), Ws [32][132] @1152 (4224) ends 5376
//   phase2: Hs [32][132] @0 (4224), W2s [32][129] @4224 (4128) ends 8352
//   qS [32][32] @8352 (1024), idxS [32][16] @9376 (512), wS @9888 (512)
//   total = 10400 floats = 41600 bytes
#define SM_WS    1152
#define SM_W2S   4224
#define SM_QS    8352
#define SM_IDX   9376
#define SM_W     9888
#define SM_TOTAL 10400

__device__ __forceinline__ unsigned mono_f(float x) {
    unsigned u = __float_as_uint(x);
    return u ^ (unsigned)(((int)u >> 31) | 0x80000000);
}

__global__ __launch_bounds__(256, 2) void fused_kernel(
    const float* __restrict__ x,  const float* __restrict__ W1,
    const float* __restrict__ b1, const float* __restrict__ W2,
    const float* __restrict__ b2, const float* __restrict__ keys,
    const float* __restrict__ values, float* __restrict__ out)
{
    extern __shared__ float smem[];
    float* Xs  = smem;             // [32][36]
    float* Ws  = smem + SM_WS;     // [32][132] k-major
    float* Hs  = smem;             // [32][132]
    float* W2s = smem + SM_W2S;    // [32][129] (c,k)
    float* qS  = smem + SM_QS;     // [32][32]
    int*   idxS = (int*)(smem + SM_IDX);   // [32][16]
    float* wS  = smem + SM_W;      // [32][16]

    const int tid  = threadIdx.x;
    const int lane = tid & 31;
    const int wid  = tid >> 5;              // 0..7
    const int block_row = blockIdx.x * 32;

    // ---------------- Phase 1: h = relu(x @ W1^T + b1) -------------------
    const int tcol = lane * 4;              // 0..124
    const int trow = wid * 4;               // 0..28
    const int xr = tid >> 3;                // 0..31
    const int xk = (tid & 7) * 4;           // 0..28

    float acc[4][4];
#pragma unroll
    for (int r = 0; r < 4; r++)
#pragma unroll
        for (int c = 0; c < 4; c++) acc[r][c] = 0.f;

    const float* xBase = x + (size_t)block_row * D_IN;

    for (int k0 = 0; k0 < D_IN; k0 += 32) {
        // X tile: 32x32 = 256 float4, one per thread
        float4 xv = *(const float4*)(xBase + (size_t)xr * D_IN + k0 + xk);
        // W1 tile: 128 rows x 32 cols = 1024 float4, 4 per thread
        float4 wv[4];
#pragma unroll
        for (int i = 0; i < 4; i++) {
            int j = tid + i * 256;
            int n = j >> 3, kq = (j & 7) * 4;
            wv[i] = *(const float4*)(W1 + (size_t)n * D_IN + k0 + kq);
        }
        __syncthreads();
        *(float4*)&Xs[xr * 36 + xk] = xv;
#pragma unroll
        for (int i = 0; i < 4; i++) {
            int j = tid + i * 256;
            int n = j >> 3, kq = (j & 7) * 4;
            Ws[(kq + 0) * 132 + n] = wv[i].x;
            Ws[(kq + 1) * 132 + n] = wv[i].y;
            Ws[(kq + 2) * 132 + n] = wv[i].z;
            Ws[(kq + 3) * 132 + n] = wv[i].w;
        }
        __syncthreads();

#pragma unroll 8
        for (int k = 0; k < 32; k++) {
            float4 w4 = *(const float4*)&Ws[k * 132 + tcol];
            float xb[4];
#pragma unroll
            for (int r = 0; r < 4; r++) xb[r] = Xs[(trow + r) * 36 + k];
#pragma unroll
            for (int r = 0; r < 4; r++) {
                acc[r][0] = fmaf(xb[r], w4.x, acc[r][0]);
                acc[r][1] = fmaf(xb[r], w4.y, acc[r][1]);
                acc[r][2] = fmaf(xb[r], w4.z, acc[r][2]);
                acc[r][3] = fmaf(xb[r], w4.w, acc[r][3]);
            }
        }
    }

    __syncthreads();   // done reading Xs/Ws; Hs overlays them

    // ---------------- Phase 2: q = relu_h @ W2^T + b2 --------------------
    {
        float4 b1v = *(const float4*)&b1[tcol];
#pragma unroll
        for (int r = 0; r < 4; r++) {
            float4 hv;
            hv.x = fmaxf(acc[r][0] + b1v.x, 0.f);
            hv.y = fmaxf(acc[r][1] + b1v.y, 0.f);
            hv.z = fmaxf(acc[r][2] + b1v.z, 0.f);
            hv.w = fmaxf(acc[r][3] + b1v.w, 0.f);
            *(float4*)&Hs[(trow + r) * 132 + tcol] = hv;
        }
        for (int i = tid; i < 32 * 128; i += 256) {
            int c = i >> 7, k = i & 127;
            W2s[c * 129 + k] = W2[i];
        }
    }
    __syncthreads();

    {
        const int rr = tid >> 3;            // 0..31
        const int cb = (tid & 7) * 4;       // 0..28
        float a2[4] = {0.f, 0.f, 0.f, 0.f};
#pragma unroll 4
        for (int k = 0; k < H1; k++) {
            float hv = Hs[rr * 132 + k];
            a2[0] = fmaf(hv, W2s[(cb + 0) * 129 + k], a2[0]);
            a2[1] = fmaf(hv, W2s[(cb + 1) * 129 + k], a2[1]);
            a2[2] = fmaf(hv, W2s[(cb + 2) * 129 + k], a2[2]);
            a2[3] = fmaf(hv, W2s[(cb + 3) * 129 + k], a2[3]);
        }
        float4 qv;
        qv.x = a2[0] + b2[cb + 0];
        qv.y = a2[1] + b2[cb + 1];
        qv.z = a2[2] + b2[cb + 2];
        qv.w = a2[3] + b2[cb + 3];
        *(float4*)&qS[rr * QD + cb] = qv;
    }
    __syncthreads();

    // ---------------- Phase 3: topk per (token, head), redux-based -------
    for (int task = wid; task < 64; task += 8) {
        const int tl = task >> 1, h = task & 1;
        const float* qp = &qS[tl * QD + h * 16];

        float q1v[HALF], q2v[HALF];
#pragma unroll
        for (int c = 0; c < HALF; c++) { q1v[c] = qp[c]; q2v[c] = qp[HALF + c]; }

        float s1[8], s2[8];
        {
            const float4* k1 = (const float4*)(keys + ((size_t)(h * 2 + 0) * NKEYS + lane * 8) * HALF);
            const float4* k2 = (const float4*)(keys + ((size_t)(h * 2 + 1) * NKEYS + lane * 8) * HALF);
#pragma unroll
            for (int j = 0; j < 8; j++) {
                float4 u1 = k1[j * 2], v1 = k1[j * 2 + 1];
                float4 u2 = k2[j * 2], v2 = k2[j * 2 + 1];
                float a = 0.f, b = 0.f;
                a = fmaf(q1v[0], u1.x, a); a = fmaf(q1v[1], u1.y, a);
                a = fmaf(q1v[2], u1.z, a); a = fmaf(q1v[3], u1.w, a);
                a = fmaf(q1v[4], v1.x, a); a = fmaf(q1v[5], v1.y, a);
                a = fmaf(q1v[6], v1.z, a); a = fmaf(q1v[7], v1.w, a);
                b = fmaf(q2v[0], u2.x, b); b = fmaf(q2v[1], u2.y, b);
                b = fmaf(q2v[2], u2.z, b); b = fmaf(q2v[3], u2.w, b);
                b = fmaf(q2v[4], v2.x, b); b = fmaf(q2v[5], v2.y, b);
                b = fmaf(q2v[6], v2.z, b); b = fmaf(q2v[7], v2.w, b);
                s1[j] = a; s2[j] = b;
            }
        }

        float my_sc1 = 0.f, my_sc2 = 0.f;
        int   my_i1 = 0, my_i2 = 0;

        // top-8 of s1 (ties -> lowest flat index, matching lax.top_k)
#pragma unroll
        for (int sel = 0; sel < 8; sel++) {
            float m = s1[0]; int mi = 0;
#pragma unroll
            for (int i = 1; i < 8; i++) if (s1[i] > m) { m = s1[i]; mi = i; }
            unsigned mm = mono_f(m);
            unsigned gm = __reduce_max_sync(FULLMASK, mm);
            unsigned bal = __ballot_sync(FULLMASK, mm == gm);
            int win = __ffs(bal) - 1;
            int   wmi = __shfl_sync(FULLMASK, mi, win);
            float wsc = __shfl_sync(FULLMASK, m, win);
            if (lane == sel) { my_sc1 = wsc; my_i1 = win * 8 + wmi; }
#pragma unroll
            for (int i = 0; i < 8; i++)
                if (lane == win && wmi == i) s1[i] = -INFINITY;
        }

#pragma unroll
        for (int sel = 0; sel < 8; sel++) {
            float m = s2[0]; int mi = 0;
#pragma unroll
            for (int i = 1; i < 8; i++) if (s2[i] > m) { m = s2[i]; mi = i; }
            unsigned mm = mono_f(m);
            unsigned gm = __reduce_max_sync(FULLMASK, mm);
            unsigned bal = __ballot_sync(FULLMASK, mm == gm);
            int win = __ffs(bal) - 1;
            int   wmi = __shfl_sync(FULLMASK, mi, win);
            float wsc = __shfl_sync(FULLMASK, m, win);
            if (lane == sel) { my_sc2 = wsc; my_i2 = win * 8 + wmi; }
#pragma unroll
            for (int i = 0; i < 8; i++)
                if (lane == win && wmi == i) s2[i] = -INFINITY;
        }

        // 64 combos, flat p = i*8+j; lane covers p=lane and p=lane+32
        float a0 = __shfl_sync(FULLMASK, my_sc1, lane >> 3);
        float a1 = __shfl_sync(FULLMASK, my_sc1, (lane >> 3) + 4);
        float b0 = __shfl_sync(FULLMASK, my_sc2, lane & 7);
        float cv0 = a0 + b0;
        float cv1 = a1 + b0;

        float my_fsc = -INFINITY; int my_fp = 0;
#pragma unroll
        for (int sel = 0; sel < 8; sel++) {
            float m = (cv0 >= cv1) ? cv0 : cv1;
            unsigned mm = mono_f(m);
            unsigned gm = __reduce_max_sync(FULLMASK, mm);
            unsigned bal0 = __ballot_sync(FULLMASK, mono_f(cv0) == gm);
            unsigned bal1 = __ballot_sync(FULLMASK, mono_f(cv1) == gm);
            int p_win = bal0 ? (__ffs(bal0) - 1) : (31 + __ffs(bal1));
            int winlane = p_win & 31;
            float wsc = __shfl_sync(FULLMASK, m, winlane);
            if (lane == sel) { my_fsc = wsc; my_fp = p_win; }
            if (lane == winlane) {
                if (p_win < 32) cv0 = -INFINITY; else cv1 = -INFINITY;
            }
        }

        // softmax over the 8 winners (lane 0 holds the max)
        float mx = __shfl_sync(FULLMASK, my_fsc, 0);
        float e = expf(my_fsc - mx);       // lanes >= 8: exp(-inf) = 0
        float sum = e;
#pragma unroll
        for (int off = 16; off; off >>= 1) sum += __shfl_xor_sync(FULLMASK, sum, off);
        float inv = 1.f / sum;

        int p  = my_fp;
        int ia = __shfl_sync(FULLMASK, my_i1, (p >> 3) & 31);
        int ib = __shfl_sync(FULLMASK, my_i2, p & 7);

        if (lane < 8) {
            idxS[tl * 16 + h * 8 + lane] = ia * NKEYS + ib;
            wS  [tl * 16 + h * 8 + lane] = e * inv;
        }
    }
    __syncthreads();

    // ---------------- Phase 4: gather (2-token interleave for MLP) -------
    for (int tl = 0; tl < 32; tl += 2) {
        float4 acc0 = make_float4(0.f, 0.f, 0.f, 0.f);
        float4 acc1 = make_float4(0.f, 0.f, 0.f, 0.f);
#pragma unroll
        for (int k = 0; k < 16; k++) {
            int   i0 = idxS[tl * 16 + k];
            float w0 = wS [tl * 16 + k];
            int   i1 = idxS[(tl + 1) * 16 + k];
            float w1 = wS [(tl + 1) * 16 + k];
            float4 v0 = ((const float4*)(values + ((size_t)i0 << 10)))[tid];
            float4 v1 = ((const float4*)(values + ((size_t)i1 << 10)))[tid];
            acc0.x = fmaf(w0, v0.x, acc0.x);
            acc0.y = fmaf(w0, v0.y, acc0.y);
            acc0.z = fmaf(w0, v0.z, acc0.z);
            acc0.w = fmaf(w0, v0.w, acc0.w);
            acc1.x = fmaf(w1, v1.x, acc1.x);
            acc1.y = fmaf(w1, v1.y, acc1.y);
            acc1.z = fmaf(w1, v1.z, acc1.z);
            acc1.w = fmaf(w1, v1.w, acc1.w);
        }
        ((float4*)(out + ((size_t)(block_row + tl)     << 10)))[tid] = acc0;
        ((float4*)(out + ((size_t)(block_row + tl + 1) << 10)))[tid] = acc1;
    }
}

extern "C" void kernel_launch(void* const* d_in, const int* in_sizes, int n_in,
                              void* d_out, int out_size)
{
    const float* x      = (const float*)d_in[0];
    const float* W1     = (const float*)d_in[1];
    const float* b1     = (const float*)d_in[2];
    const float* W2     = (const float*)d_in[3];
    const float* b2     = (const float*)d_in[4];
    const float* keys   = (const float*)d_in[5];
    const float* values = (const float*)d_in[6];
    float* out = (float*)d_out;

    const int T = in_sizes[0] / D_IN;   // 8192
    const int smemB = SM_TOTAL * (int)sizeof(float);  // 41600

    cudaFuncSetAttribute(fused_kernel,
                         cudaFuncAttributeMaxDynamicSharedMemorySize, smemB);

    fused_kernel<<<T / 32, 256, smemB>>>(x, W1, b1, W2, b2, keys, values, out);
}